// round 12
// baseline (speedup 1.0000x reference)
#include <cuda_runtime.h>
#include <math.h>
#include <cstdint>

typedef unsigned long long u64;

// ---------------------------------------------------------------------------
// Problem constants
// ---------------------------------------------------------------------------
#define BB   16
#define LL   512
#define EMB  300
#define AH   256
#define ATT  250
#define HH   128
#define ATT_IN 812
#define RNN_IN 1280
#define GATES  512
#define ROWS 8192
#define K1P  816        // ATT_IN padded to 16
#define NW   768        // 3 modules x 256 (ATT padded)

// GEMM dynamic smem layout
#define ASTR 268                      // A dup'd row stride (floats), 16B-aligned
#define BSTR 132
#define ABYTES (2 * 16 * ASTR * 4)    // 34304
#define GSMEM  (ABYTES + 2 * 16 * BSTR * 4)   // 51200

// ---------------------------------------------------------------------------
// Scratch (fp32 everywhere)
// ---------------------------------------------------------------------------
__device__ float g_x1a[ROWS * K1P];
__device__ float g_x2a[ROWS * K1P];
__device__ float g_Wc[NW * K1P];
__device__ float g_r1[ROWS * NW];
__device__ float g_r2[ROWS * NW];
__device__ float g_sc[3ll * BB * LL * LL];
__device__ float g_x2T[3ll * BB * AH * LL];
__device__ float g_x1c[(long long)ROWS * RNN_IN];
__device__ float g_Wih[1024 * RNN_IN];
__device__ float g_gin[(long long)ROWS * 1024];

// ---------------------------------------------------------------------------
// f32x2 helpers
// ---------------------------------------------------------------------------
__device__ __forceinline__ void ffma2(u64& d, u64 a, u64 b) {
    asm("fma.rn.f32x2 %0, %1, %2, %0;" : "+l"(d) : "l"(a), "l"(b));
}
__device__ __forceinline__ u64 dup2(float x) {
    u64 r; asm("mov.b64 %0, {%1, %1};" : "=l"(r) : "f"(x)); return r;
}
__device__ __forceinline__ void unpack2(u64 v, float& x, float& y) {
    asm("mov.b64 {%0, %1}, %2;" : "=f"(x), "=f"(y) : "l"(v));
}

// ---------------------------------------------------------------------------
// Prep kernels
// ---------------------------------------------------------------------------
__global__ void bx1(const float* __restrict__ w, const float* __restrict__ a0,
                    const float* __restrict__ a1, float* __restrict__ out) {
    long long idx = (long long)blockIdx.x * blockDim.x + threadIdx.x;
    if (idx >= (long long)ROWS * K1P) return;
    int r = (int)(idx / K1P), k = (int)(idx % K1P);
    float x = 0.f;
    if (k < EMB)            x = w[r * EMB + k];
    else if (k < EMB + AH)  x = a0[r * AH + (k - EMB)];
    else if (k < ATT_IN)    x = a1[r * AH + (k - EMB - AH)];
    out[idx] = x;
}

__global__ void bW(const float* __restrict__ W, float* __restrict__ out) {
    long long idx = (long long)blockIdx.x * blockDim.x + threadIdx.x;
    if (idx >= (long long)NW * K1P) return;
    int row = (int)(idx / K1P), k = (int)(idx % K1P);
    int m = row >> 8, r = row & 255;
    out[idx] = (r < ATT && k < ATT_IN)
             ? W[((long long)m * ATT + r) * ATT_IN + k] : 0.f;
}

__global__ void bWih(const float* __restrict__ Wf, const float* __restrict__ Wb,
                     float* __restrict__ out) {
    long long idx = (long long)blockIdx.x * blockDim.x + threadIdx.x;
    if (idx >= (long long)1024 * RNN_IN) return;
    int row = (int)(idx / RNN_IN), k = (int)(idx % RNN_IN);
    out[idx] = (row < 512) ? Wf[(long long)row * RNN_IN + k]
                           : Wb[(long long)(row - 512) * RNN_IN + k];
}

__global__ void bcat(const float* __restrict__ a0, const float* __restrict__ a1,
                     float* __restrict__ out) {
    long long idx = (long long)blockIdx.x * blockDim.x + threadIdx.x;
    if (idx >= (long long)ROWS * 2 * AH) return;
    int r = (int)(idx / (2 * AH)), d = (int)(idx % (2 * AH));
    float x = (d < AH) ? a0[r * AH + d] : a1[r * AH + (d - AH)];
    out[(long long)r * RNN_IN + d] = x;
}

// [16][512][256] -> [16][256][512]
__global__ void btr(const float* __restrict__ in, float* __restrict__ out) {
    __shared__ float tile[32][33];
    int b = blockIdx.z;
    int lBase = blockIdx.x * 32, dBase = blockIdx.y * 32;
    const float* ib = in + (long long)b * LL * AH;
    int tx = threadIdx.x, ty = threadIdx.y;   // 32 x 8
#pragma unroll
    for (int i = 0; i < 32; i += 8)
        tile[ty + i][tx] = ib[(long long)(lBase + ty + i) * AH + dBase + tx];
    __syncthreads();
    float* ob = out + (long long)b * AH * LL;
#pragma unroll
    for (int i = 0; i < 32; i += 8)
        ob[(long long)(dBase + ty + i) * LL + lBase + tx] = tile[tx][ty + i];
}

// ---------------------------------------------------------------------------
// fp32 NT GEMM via fma.rn.f32x2.  C = epi(A @ B^T)
// A-tile stored DUPLICATED in smem ([k][2m]=[k][2m+1]) so fragment loads are
// dup'd u64 pairs directly -> zero movs in the inner loop (32 FFMA2 + 6 LDS).
// ---------------------------------------------------------------------------
__global__ __launch_bounds__(256, 2)
void gemm_f32(const float* __restrict__ A, const float* __restrict__ B,
              float* __restrict__ C,
              int lda, int ldb, int ldc, int nst,
              long long aHi, long long aLo, long long bHi, long long bLo,
              long long cHi, long long cLo,
              const float* __restrict__ bias0, const float* __restrict__ bias1,
              const float* __restrict__ vsc, int mode) {
    extern __shared__ float smem[];
    float* As_ = smem;                      // [buf][16][ASTR] dup'd
    float* Bs_ = smem + 2 * 16 * ASTR;      // [buf][16][BSTR]
#define ASP(buf, k) (As_ + ((buf) * 16 + (k)) * ASTR)
#define BSP(buf, k) (Bs_ + ((buf) * 16 + (k)) * BSTR)

    const int t = threadIdx.x;
    const int tx = t & 15, ty = t >> 4;
    const int m0 = blockIdx.y * 128, n0 = blockIdx.x * 128;
    const int zHi = blockIdx.z >> 4, zLo = blockIdx.z & 15;
    const float* Ag = A + (long long)zHi * aHi + (long long)zLo * aLo;
    const float* Bg = B + (long long)zHi * bHi + (long long)zLo * bLo;

    u64 acc[8][4];
#pragma unroll
    for (int i = 0; i < 8; i++)
#pragma unroll
        for (int j = 0; j < 4; j++) acc[i][j] = 0ull;

    const int lr = t >> 2, lc = t & 3;
    float4 ra0, ra1, rb0, rb1;

    auto LOADG = [&](int s) {
        const float* pa = Ag + (long long)(m0 + lr) * lda + s * 16 + lc * 4;
        ra0 = *(const float4*)pa;
        ra1 = *(const float4*)(pa + 64ll * lda);
        const float* pb = Bg + (long long)(n0 + lr) * ldb + s * 16 + lc * 4;
        rb0 = *(const float4*)pb;
        rb1 = *(const float4*)(pb + 64ll * ldb);
    };
    auto STS = [&](int buf) {
        // A dup'd: ST.64 of (v,v) at [kk][2m]
        *(u64*)&ASP(buf, lc * 4 + 0)[2 * lr] = dup2(ra0.x);
        *(u64*)&ASP(buf, lc * 4 + 1)[2 * lr] = dup2(ra0.y);
        *(u64*)&ASP(buf, lc * 4 + 2)[2 * lr] = dup2(ra0.z);
        *(u64*)&ASP(buf, lc * 4 + 3)[2 * lr] = dup2(ra0.w);
        *(u64*)&ASP(buf, lc * 4 + 0)[2 * (lr + 64)] = dup2(ra1.x);
        *(u64*)&ASP(buf, lc * 4 + 1)[2 * (lr + 64)] = dup2(ra1.y);
        *(u64*)&ASP(buf, lc * 4 + 2)[2 * (lr + 64)] = dup2(ra1.z);
        *(u64*)&ASP(buf, lc * 4 + 3)[2 * (lr + 64)] = dup2(ra1.w);
        BSP(buf, lc * 4 + 0)[lr] = rb0.x;
        BSP(buf, lc * 4 + 1)[lr] = rb0.y;
        BSP(buf, lc * 4 + 2)[lr] = rb0.z;
        BSP(buf, lc * 4 + 3)[lr] = rb0.w;
        BSP(buf, lc * 4 + 0)[lr + 64] = rb1.x;
        BSP(buf, lc * 4 + 1)[lr + 64] = rb1.y;
        BSP(buf, lc * 4 + 2)[lr + 64] = rb1.z;
        BSP(buf, lc * 4 + 3)[lr + 64] = rb1.w;
    };
    auto COMP = [&](int buf) {
#pragma unroll
        for (int k = 0; k < 16; k++) {
            const float* ar = ASP(buf, k) + ty * 16;
            ulonglong2 d01 = *(const ulonglong2*)(ar);
            ulonglong2 d23 = *(const ulonglong2*)(ar + 4);
            ulonglong2 d45 = *(const ulonglong2*)(ar + 8);
            ulonglong2 d67 = *(const ulonglong2*)(ar + 12);
            const float* br = BSP(buf, k) + tx * 8;
            ulonglong2 b01 = *(const ulonglong2*)(br);
            ulonglong2 b23 = *(const ulonglong2*)(br + 4);
            u64 ad[8] = {d01.x, d01.y, d23.x, d23.y, d45.x, d45.y, d67.x, d67.y};
            u64 bp[4] = {b01.x, b01.y, b23.x, b23.y};
#pragma unroll
            for (int i = 0; i < 8; i++) {
                ffma2(acc[i][0], ad[i], bp[0]);
                ffma2(acc[i][1], ad[i], bp[1]);
                ffma2(acc[i][2], ad[i], bp[2]);
                ffma2(acc[i][3], ad[i], bp[3]);
            }
        }
    };

    LOADG(0);
    STS(0);
    __syncthreads();
    for (int s = 0; s < nst; s++) {
        if (s + 1 < nst) LOADG(s + 1);
        COMP(s & 1);
        if (s + 1 < nst) {
            STS((s + 1) & 1);
            __syncthreads();
        }
    }

    float* Cg = C + (long long)zHi * cHi + (long long)zLo * cLo;
#pragma unroll
    for (int i = 0; i < 8; i++) {
        int gr = m0 + ty * 8 + i;
#pragma unroll
        for (int j = 0; j < 4; j++) {
            float vx, vy;
            unpack2(acc[i][j], vx, vy);
            int gc = n0 + tx * 8 + j * 2;
            if (mode == 1) {
                vx = fmaxf(vx, 0.f); vy = fmaxf(vy, 0.f);
                if (vsc) {
                    int mo = gc >> 8, c = gc & 255;
                    vx *= (c < ATT) ? vsc[mo * ATT + c] : 0.f;
                    vy *= (c + 1 < ATT) ? vsc[mo * ATT + c + 1] : 0.f;
                }
            } else if (mode == 2) {
                vx += (gc < 512) ? bias0[gc] : bias1[gc - 512];
                vy += (gc + 1 < 512) ? bias0[gc + 1] : bias1[gc - 511];
            }
            float2 w; w.x = vx; w.y = vy;
            *(float2*)(Cg + (long long)gr * ldc + gc) = w;
        }
    }
#undef ASP
#undef BSP
}

// ---------------------------------------------------------------------------
// Masked row softmax over L2, in place (fp32).  rows = [module][b][l]
// ---------------------------------------------------------------------------
__global__ void softmax_kernel(float* __restrict__ S,
                               const unsigned char* __restrict__ mask) {
    int row = blockIdx.x;
    int b = (row >> 9) & 15;
    float* s = S + (long long)row * LL;
    const unsigned char* m = mask + (long long)b * LL;
    int t = threadIdx.x;

    __shared__ float red[256];

    float mx = -3.402823466e38f;
    for (int i = t; i < LL; i += 256) {
        float v = m[i] ? -3.402823466e38f : s[i];
        s[i] = v;
        mx = fmaxf(mx, v);
    }
    red[t] = mx; __syncthreads();
    for (int o = 128; o > 0; o >>= 1) {
        if (t < o) red[t] = fmaxf(red[t], red[t + o]);
        __syncthreads();
    }
    mx = red[0]; __syncthreads();

    float sum = 0.f;
    for (int i = t; i < LL; i += 256) {
        float e = __expf(s[i] - mx);
        s[i] = e;
        sum += e;
    }
    red[t] = sum; __syncthreads();
    for (int o = 128; o > 0; o >>= 1) {
        if (t < o) red[t] += red[t + o];
        __syncthreads();
    }
    float inv = 1.f / red[0];
    for (int i = t; i < LL; i += 256) s[i] *= inv;
}

// ---------------------------------------------------------------------------
// BiLSTM recurrence.  W register/smem-resident + gin prefetched 2 steps ahead
// so the per-step LDG latency overlaps the FFMA chain.
// ---------------------------------------------------------------------------
#define LS_SW_BYTES (512 * 22 * 8)
#define LS_SMEM (LS_SW_BYTES + 128 * 4 + 512 * 4)

__device__ __forceinline__ float fsig(float x) {
    return __fdividef(1.f, 1.f + __expf(-x));
}
__device__ __forceinline__ float ftanh(float x) {
    float e = __expf(-2.f * x);
    return __fdividef(1.f - e, 1.f + e);
}

__global__ __launch_bounds__(512, 1)
void lstm_kernel(const float* __restrict__ gin,
                 const float* __restrict__ Whh_f, const float* __restrict__ Whh_b,
                 float* __restrict__ out) {
    extern __shared__ char ls[];
    u64* sw = (u64*)ls;
    float* h_s = (float*)(ls + LS_SW_BYTES);
    float* z_s = h_s + 128;

    int blk = blockIdx.x;
    int dir = blk >> 4;
    int b = blk & 15;
    const float* W = dir ? Whh_b : Whh_f;
    int t = threadIdx.x;

    // Load W row: k [0,88) -> regs, k [88,128) -> smem
    u64 wreg[44];
    const float* wr = W + t * HH;
#pragma unroll
    for (int i = 0; i < 44; i++) wreg[i] = *(const u64*)(wr + 2 * i);
    u64* swr = sw + t * 22;
#pragma unroll
    for (int i = 0; i < 20; i++) swr[i] = *(const u64*)(wr + 88 + 2 * i);

    if (t < 128) h_s[t] = 0.f;
    float c = 0.f;
    __syncthreads();

    const u64* hp = (const u64*)h_s;    // 64 f32x2 pairs

    // gin walk with prefetch depth 2
    const long long gstride = dir ? -1024 : 1024;
    const float* gp = gin + (long long)(b * LL + (dir ? LL - 1 : 0)) * 1024
                    + dir * 512 + t;
    float p0 = gp[0];
    float p1 = gp[gstride];
    gp += 2 * gstride;

    for (int step = 0; step < LL; step++) {
        float p2 = 0.f;
        if (step + 2 < LL) p2 = *gp;
        gp += gstride;
        float base = p0;
        p0 = p1; p1 = p2;

        u64 a0 = 0ull, a1 = 0ull, a2 = 0ull, a3 = 0ull;
#pragma unroll
        for (int i = 0; i < 44; i += 4) {
            ffma2(a0, wreg[i],     hp[i]);
            ffma2(a1, wreg[i + 1], hp[i + 1]);
            ffma2(a2, wreg[i + 2], hp[i + 2]);
            ffma2(a3, wreg[i + 3], hp[i + 3]);
        }
#pragma unroll
        for (int i = 0; i < 20; i += 4) {
            ffma2(a0, swr[i],     hp[44 + i]);
            ffma2(a1, swr[i + 1], hp[44 + i + 1]);
            ffma2(a2, swr[i + 2], hp[44 + i + 2]);
            ffma2(a3, swr[i + 3], hp[44 + i + 3]);
        }
        float x0, y0, x1, y1, x2, y2, x3, y3;
        unpack2(a0, x0, y0); unpack2(a1, x1, y1);
        unpack2(a2, x2, y2); unpack2(a3, x3, y3);
        z_s[t] = base + ((x0 + y0) + (x1 + y1)) + ((x2 + y2) + (x3 + y3));
        __syncthreads();

        if (t < 128) {
            int l = dir ? (LL - 1 - step) : step;
            float zi = z_s[t], zf = z_s[128 + t], zg = z_s[256 + t], zo = z_s[384 + t];
            float ig = fsig(zi);
            float fg = fsig(zf);
            float gg = ftanh(zg);
            float og = fsig(zo);
            c = fg * c + ig * gg;
            float h = og * ftanh(c);
            h_s[t] = h;
            out[((long long)(b * LL + l)) * 256 + dir * HH + t] = h;
        }
        __syncthreads();
    }
}

// ---------------------------------------------------------------------------
// Launch orchestration
// ---------------------------------------------------------------------------
static void* symaddr(const void* sym) {
    void* p = nullptr;
    cudaGetSymbolAddress(&p, sym);
    return p;
}

extern "C" void kernel_launch(void* const* d_in, const int* in_sizes, int n_in,
                              void* d_out, int out_size) {
    const float* x1_word = (const float*)d_in[0];
    const float* x1_a0   = (const float*)d_in[1];
    const float* x1_a1   = (const float*)d_in[2];
    const float* x2_word = (const float*)d_in[3];
    const float* x2_a0   = (const float*)d_in[4];
    const float* x2_a1   = (const float*)d_in[5];
    const float* x2_a2   = (const float*)d_in[6];
    const unsigned char* x2_mask = (const unsigned char*)d_in[8];
    const float* W_attn  = (const float*)d_in[9];
    const float* v_attn  = (const float*)d_in[10];
    const float* Wih_f   = (const float*)d_in[11];
    const float* Whh_f   = (const float*)d_in[12];
    const float* b_f     = (const float*)d_in[13];
    const float* Wih_b   = (const float*)d_in[14];
    const float* Whh_b   = (const float*)d_in[15];
    const float* b_b     = (const float*)d_in[16];
    float* out = (float*)d_out;

    float* x1a = (float*)symaddr(g_x1a);
    float* x2a = (float*)symaddr(g_x2a);
    float* Wc  = (float*)symaddr(g_Wc);
    float* r1  = (float*)symaddr(g_r1);
    float* r2  = (float*)symaddr(g_r2);
    float* sc  = (float*)symaddr(g_sc);
    float* x2T = (float*)symaddr(g_x2T);
    float* x1c = (float*)symaddr(g_x1c);
    float* Wih = (float*)symaddr(g_Wih);
    float* gin = (float*)symaddr(g_gin);

    cudaFuncSetAttribute(gemm_f32, cudaFuncAttributeMaxDynamicSharedMemorySize,
                         GSMEM);
    cudaFuncSetAttribute(lstm_kernel, cudaFuncAttributeMaxDynamicSharedMemorySize,
                         LS_SMEM);

    const float* x2_list[3] = {x2_a0, x2_a1, x2_a2};

    // prep
    {
        long long n1 = (long long)ROWS * K1P;
        bx1<<<(int)((n1 + 255) / 256), 256>>>(x1_word, x1_a0, x1_a1, x1a);
        bx1<<<(int)((n1 + 255) / 256), 256>>>(x2_word, x2_a0, x2_a1, x2a);
        long long nw = (long long)NW * K1P;
        bW<<<(int)((nw + 255) / 256), 256>>>(W_attn, Wc);
    }

    // r1 = relu(x1_att @ Wc^T)   [8192 x 768], K=816
    gemm_f32<<<dim3(6, 64, 1), 256, GSMEM>>>(
        x1a, Wc, r1, K1P, K1P, NW, K1P / 16,
        0, 0, 0, 0, 0, 0, nullptr, nullptr, nullptr, 1);

    // r2 = relu(x2_att @ Wc^T) * v
    gemm_f32<<<dim3(6, 64, 1), 256, GSMEM>>>(
        x2a, Wc, r2, K1P, K1P, NW, K1P / 16,
        0, 0, 0, 0, 0, 0, nullptr, nullptr, v_attn, 1);

    // remaining prep
    {
        long long nh = (long long)1024 * RNN_IN;
        bWih<<<(int)((nh + 255) / 256), 256>>>(Wih_f, Wih_b, Wih);
        long long nc = (long long)ROWS * 2 * AH;
        bcat<<<(int)((nc + 255) / 256), 256>>>(x1_a0, x1_a1, x1c);
        dim3 tg(LL / 32, AH / 32, BB), tb(32, 8);
        for (int i = 0; i < 3; i++)
            btr<<<tg, tb>>>(x2_list[i], x2T + (long long)i * BB * AH * LL);
    }

    // scores[m][b] = r1_sub @ r2_sub^T   (z = m*16+b), K=256
    gemm_f32<<<dim3(4, 4, 48), 256, GSMEM>>>(
        r1, r2, sc, NW, NW, LL, 256 / 16,
        256, (long long)LL * NW,
        256, (long long)LL * NW,
        (long long)BB * LL * LL, (long long)LL * LL,
        nullptr, nullptr, nullptr, 0);

    // softmax in place
    softmax_kernel<<<3 * ROWS, 256>>>(sc, x2_mask);

    // piece[m][b] = alpha @ x2T^T -> x1cat cols [512+256m, +256), K=512
    gemm_f32<<<dim3(2, 4, 48), 256, GSMEM>>>(
        sc, x2T, x1c + 512, LL, LL, RNN_IN, LL / 16,
        (long long)BB * LL * LL, (long long)LL * LL,
        (long long)BB * AH * LL, (long long)AH * LL,
        256, (long long)LL * RNN_IN,
        nullptr, nullptr, nullptr, 0);

    // gin = x1cat @ Wih^T + bias   [8192 x 1024], K=1280
    gemm_f32<<<dim3(8, 64, 1), 256, GSMEM>>>(
        x1c, Wih, gin, RNN_IN, RNN_IN, 1024, RNN_IN / 16,
        0, 0, 0, 0, 0, 0, b_f, b_b, nullptr, 2);

    // recurrence
    lstm_kernel<<<32, 512, LS_SMEM>>>(gin, Whh_f, Whh_b, out);
}

// round 13
// speedup vs baseline: 1.1429x; 1.1429x over previous
#include <cuda_runtime.h>
#include <math.h>
#include <cstdint>

typedef unsigned long long u64;

// ---------------------------------------------------------------------------
// Problem constants
// ---------------------------------------------------------------------------
#define BB   16
#define LL   512
#define EMB  300
#define AH   256
#define ATT  250
#define HH   128
#define ATT_IN 812
#define RNN_IN 1280
#define GATES  512
#define ROWS 8192
#define K1P  816        // ATT_IN padded to 16
#define NW   768        // 3 modules x 256 (ATT padded)

// ---------------------------------------------------------------------------
// Scratch (fp32 everywhere)
// ---------------------------------------------------------------------------
__device__ float g_x1a[ROWS * K1P];
__device__ float g_x2a[ROWS * K1P];
__device__ float g_Wc[NW * K1P];
__device__ float g_r1[ROWS * NW];
__device__ float g_r2[ROWS * NW];
__device__ float g_sc[3ll * BB * LL * LL];
__device__ float g_x2T[3ll * BB * AH * LL];
__device__ float g_x1c[(long long)ROWS * RNN_IN];
__device__ float g_Wih[1024 * RNN_IN];
__device__ float g_gin[(long long)ROWS * 1024];

// ---------------------------------------------------------------------------
// f32x2 helpers
// ---------------------------------------------------------------------------
__device__ __forceinline__ void ffma2(u64& d, u64 a, u64 b) {
    asm("fma.rn.f32x2 %0, %1, %2, %0;" : "+l"(d) : "l"(a), "l"(b));
}
__device__ __forceinline__ u64 dup2(float x) {
    u64 r; asm("mov.b64 %0, {%1, %1};" : "=l"(r) : "f"(x)); return r;
}
__device__ __forceinline__ void unpack2(u64 v, float& x, float& y) {
    asm("mov.b64 {%0, %1}, %2;" : "=f"(x), "=f"(y) : "l"(v));
}

// ---------------------------------------------------------------------------
// Prep kernels
// ---------------------------------------------------------------------------
__global__ void bx1(const float* __restrict__ w, const float* __restrict__ a0,
                    const float* __restrict__ a1, float* __restrict__ out) {
    long long idx = (long long)blockIdx.x * blockDim.x + threadIdx.x;
    if (idx >= (long long)ROWS * K1P) return;
    int r = (int)(idx / K1P), k = (int)(idx % K1P);
    float x = 0.f;
    if (k < EMB)            x = w[r * EMB + k];
    else if (k < EMB + AH)  x = a0[r * AH + (k - EMB)];
    else if (k < ATT_IN)    x = a1[r * AH + (k - EMB - AH)];
    out[idx] = x;
}

__global__ void bW(const float* __restrict__ W, float* __restrict__ out) {
    long long idx = (long long)blockIdx.x * blockDim.x + threadIdx.x;
    if (idx >= (long long)NW * K1P) return;
    int row = (int)(idx / K1P), k = (int)(idx % K1P);
    int m = row >> 8, r = row & 255;
    out[idx] = (r < ATT && k < ATT_IN)
             ? W[((long long)m * ATT + r) * ATT_IN + k] : 0.f;
}

__global__ void bWih(const float* __restrict__ Wf, const float* __restrict__ Wb,
                     float* __restrict__ out) {
    long long idx = (long long)blockIdx.x * blockDim.x + threadIdx.x;
    if (idx >= (long long)1024 * RNN_IN) return;
    int row = (int)(idx / RNN_IN), k = (int)(idx % RNN_IN);
    out[idx] = (row < 512) ? Wf[(long long)row * RNN_IN + k]
                           : Wb[(long long)(row - 512) * RNN_IN + k];
}

__global__ void bcat(const float* __restrict__ a0, const float* __restrict__ a1,
                     float* __restrict__ out) {
    long long idx = (long long)blockIdx.x * blockDim.x + threadIdx.x;
    if (idx >= (long long)ROWS * 2 * AH) return;
    int r = (int)(idx / (2 * AH)), d = (int)(idx % (2 * AH));
    float x = (d < AH) ? a0[r * AH + d] : a1[r * AH + (d - AH)];
    out[(long long)r * RNN_IN + d] = x;
}

// [16][512][256] -> [16][256][512]
__global__ void btr(const float* __restrict__ in, float* __restrict__ out) {
    __shared__ float tile[32][33];
    int b = blockIdx.z;
    int lBase = blockIdx.x * 32, dBase = blockIdx.y * 32;
    const float* ib = in + (long long)b * LL * AH;
    int tx = threadIdx.x, ty = threadIdx.y;   // 32 x 8
#pragma unroll
    for (int i = 0; i < 32; i += 8)
        tile[ty + i][tx] = ib[(long long)(lBase + ty + i) * AH + dBase + tx];
    __syncthreads();
    float* ob = out + (long long)b * AH * LL;
#pragma unroll
    for (int i = 0; i < 32; i += 8)
        ob[(long long)(dBase + ty + i) * LL + lBase + tx] = tile[tx][ty + i];
}

// ---------------------------------------------------------------------------
// fp32 NT GEMM via fma.rn.f32x2.  C = epi(A @ B^T)  (exact R11 inner loop)
// Dual mode: if A2 != nullptr, blockIdx.z==1 switches to (A2 -> C2, *vsc);
// lets r1 and r2 share one launch to kill wave-quantization waste.
// ---------------------------------------------------------------------------
__global__ __launch_bounds__(256, 2)
void gemm_f32(const float* __restrict__ A, const float* __restrict__ B,
              float* __restrict__ C,
              const float* __restrict__ A2, float* __restrict__ C2,
              int lda, int ldb, int ldc, int nst,
              long long aHi, long long aLo, long long bHi, long long bLo,
              long long cHi, long long cLo,
              const float* __restrict__ bias0, const float* __restrict__ bias1,
              const float* __restrict__ vsc, int mode) {
    __shared__ float As[2][16][132];
    __shared__ float Bs[2][16][132];
    const int t = threadIdx.x;
    const int tx = t & 15, ty = t >> 4;
    const int m0 = blockIdx.y * 128, n0 = blockIdx.x * 128;
    const int zHi = blockIdx.z >> 4, zLo = blockIdx.z & 15;

    const float* Ag;
    float* Cbase;
    const float* vs;
    if (A2 != nullptr && blockIdx.z == 1) {
        Ag = A2; Cbase = C2; vs = vsc;
    } else {
        Ag = A + (long long)zHi * aHi + (long long)zLo * aLo;
        Cbase = C + (long long)zHi * cHi + (long long)zLo * cLo;
        vs = (A2 == nullptr) ? vsc : nullptr;
    }
    const float* Bg = B + (long long)zHi * bHi + (long long)zLo * bLo;

    u64 acc[8][4];
#pragma unroll
    for (int i = 0; i < 8; i++)
#pragma unroll
        for (int j = 0; j < 4; j++) acc[i][j] = 0ull;

    const int lr = t >> 2, lc = t & 3;
    float4 ra0, ra1, rb0, rb1;

    auto LOADG = [&](int s) {
        const float* pa = Ag + (long long)(m0 + lr) * lda + s * 16 + lc * 4;
        ra0 = *(const float4*)pa;
        ra1 = *(const float4*)(pa + 64ll * lda);
        const float* pb = Bg + (long long)(n0 + lr) * ldb + s * 16 + lc * 4;
        rb0 = *(const float4*)pb;
        rb1 = *(const float4*)(pb + 64ll * ldb);
    };
    auto STS = [&](int buf) {
        As[buf][lc * 4 + 0][lr] = ra0.x; As[buf][lc * 4 + 1][lr] = ra0.y;
        As[buf][lc * 4 + 2][lr] = ra0.z; As[buf][lc * 4 + 3][lr] = ra0.w;
        As[buf][lc * 4 + 0][lr + 64] = ra1.x; As[buf][lc * 4 + 1][lr + 64] = ra1.y;
        As[buf][lc * 4 + 2][lr + 64] = ra1.z; As[buf][lc * 4 + 3][lr + 64] = ra1.w;
        Bs[buf][lc * 4 + 0][lr] = rb0.x; Bs[buf][lc * 4 + 1][lr] = rb0.y;
        Bs[buf][lc * 4 + 2][lr] = rb0.z; Bs[buf][lc * 4 + 3][lr] = rb0.w;
        Bs[buf][lc * 4 + 0][lr + 64] = rb1.x; Bs[buf][lc * 4 + 1][lr + 64] = rb1.y;
        Bs[buf][lc * 4 + 2][lr + 64] = rb1.z; Bs[buf][lc * 4 + 3][lr + 64] = rb1.w;
    };
    auto COMP = [&](int buf) {
#pragma unroll
        for (int k = 0; k < 16; k++) {
            float4 a0 = *(const float4*)&As[buf][k][ty * 8];
            float4 a1 = *(const float4*)&As[buf][k][ty * 8 + 4];
            ulonglong2 b01 = *(const ulonglong2*)&Bs[buf][k][tx * 8];
            ulonglong2 b23 = *(const ulonglong2*)&Bs[buf][k][tx * 8 + 4];
            u64 bp[4];
            bp[0] = b01.x; bp[1] = b01.y; bp[2] = b23.x; bp[3] = b23.y;
            float av[8] = {a0.x, a0.y, a0.z, a0.w, a1.x, a1.y, a1.z, a1.w};
#pragma unroll
            for (int i = 0; i < 8; i++) {
                u64 ad = dup2(av[i]);
                ffma2(acc[i][0], ad, bp[0]);
                ffma2(acc[i][1], ad, bp[1]);
                ffma2(acc[i][2], ad, bp[2]);
                ffma2(acc[i][3], ad, bp[3]);
            }
        }
    };

    LOADG(0);
    STS(0);
    __syncthreads();
    for (int s = 0; s < nst; s++) {
        if (s + 1 < nst) LOADG(s + 1);
        COMP(s & 1);
        if (s + 1 < nst) {
            STS((s + 1) & 1);
            __syncthreads();
        }
    }

#pragma unroll
    for (int i = 0; i < 8; i++) {
        int gr = m0 + ty * 8 + i;
#pragma unroll
        for (int j = 0; j < 4; j++) {
            float vx, vy;
            unpack2(acc[i][j], vx, vy);
            int gc = n0 + tx * 8 + j * 2;
            if (mode == 1) {
                vx = fmaxf(vx, 0.f); vy = fmaxf(vy, 0.f);
                if (vs) {
                    int mo = gc >> 8, c = gc & 255;
                    vx *= (c < ATT) ? vs[mo * ATT + c] : 0.f;
                    vy *= (c + 1 < ATT) ? vs[mo * ATT + c + 1] : 0.f;
                }
            } else if (mode == 2) {
                vx += (gc < 512) ? bias0[gc] : bias1[gc - 512];
                vy += (gc + 1 < 512) ? bias0[gc + 1] : bias1[gc - 511];
            }
            float2 w; w.x = vx; w.y = vy;
            *(float2*)(Cbase + (long long)gr * ldc + gc) = w;
        }
    }
}

// ---------------------------------------------------------------------------
// Masked row softmax over L2, in place (fp32).  rows = [module][b][l]
// ---------------------------------------------------------------------------
__global__ void softmax_kernel(float* __restrict__ S,
                               const unsigned char* __restrict__ mask) {
    int row = blockIdx.x;
    int b = (row >> 9) & 15;
    float* s = S + (long long)row * LL;
    const unsigned char* m = mask + (long long)b * LL;
    int t = threadIdx.x;

    __shared__ float red[256];

    float mx = -3.402823466e38f;
    for (int i = t; i < LL; i += 256) {
        float v = m[i] ? -3.402823466e38f : s[i];
        s[i] = v;
        mx = fmaxf(mx, v);
    }
    red[t] = mx; __syncthreads();
    for (int o = 128; o > 0; o >>= 1) {
        if (t < o) red[t] = fmaxf(red[t], red[t + o]);
        __syncthreads();
    }
    mx = red[0]; __syncthreads();

    float sum = 0.f;
    for (int i = t; i < LL; i += 256) {
        float e = __expf(s[i] - mx);
        s[i] = e;
        sum += e;
    }
    red[t] = sum; __syncthreads();
    for (int o = 128; o > 0; o >>= 1) {
        if (t < o) red[t] += red[t + o];
        __syncthreads();
    }
    float inv = 1.f / red[0];
    for (int i = t; i < LL; i += 256) s[i] *= inv;
}

// ---------------------------------------------------------------------------
// BiLSTM recurrence (exact 1997us version: W in regs+smem, fast activations)
// ---------------------------------------------------------------------------
#define LS_SW_BYTES (512 * 22 * 8)
#define LS_SMEM (LS_SW_BYTES + 128 * 4 + 512 * 4)

__device__ __forceinline__ float fsig(float x) {
    return __fdividef(1.f, 1.f + __expf(-x));
}
__device__ __forceinline__ float ftanh(float x) {
    float e = __expf(-2.f * x);
    return __fdividef(1.f - e, 1.f + e);
}

__global__ __launch_bounds__(512, 1)
void lstm_kernel(const float* __restrict__ gin,
                 const float* __restrict__ Whh_f, const float* __restrict__ Whh_b,
                 float* __restrict__ out) {
    extern __shared__ char ls[];
    u64* sw = (u64*)ls;
    float* h_s = (float*)(ls + LS_SW_BYTES);
    float* z_s = h_s + 128;

    int blk = blockIdx.x;
    int dir = blk >> 4;
    int b = blk & 15;
    const float* W = dir ? Whh_b : Whh_f;
    int t = threadIdx.x;

    // Load W row: k [0,88) -> regs, k [88,128) -> smem
    u64 wreg[44];
    const float* wr = W + t * HH;
#pragma unroll
    for (int i = 0; i < 44; i++) wreg[i] = *(const u64*)(wr + 2 * i);
    u64* swr = sw + t * 22;
#pragma unroll
    for (int i = 0; i < 20; i++) swr[i] = *(const u64*)(wr + 88 + 2 * i);

    if (t < 128) h_s[t] = 0.f;
    float c = 0.f;
    __syncthreads();

    const u64* hp = (const u64*)h_s;    // 64 f32x2 pairs

    for (int step = 0; step < LL; step++) {
        int l = dir ? (LL - 1 - step) : step;
        float base = gin[((long long)(b * LL + l)) * 1024 + dir * 512 + t];

        u64 a0 = 0ull, a1 = 0ull, a2 = 0ull, a3 = 0ull;
#pragma unroll
        for (int i = 0; i < 44; i += 4) {
            ffma2(a0, wreg[i],     hp[i]);
            ffma2(a1, wreg[i + 1], hp[i + 1]);
            ffma2(a2, wreg[i + 2], hp[i + 2]);
            ffma2(a3, wreg[i + 3], hp[i + 3]);
        }
#pragma unroll
        for (int i = 0; i < 20; i += 4) {
            ffma2(a0, swr[i],     hp[44 + i]);
            ffma2(a1, swr[i + 1], hp[44 + i + 1]);
            ffma2(a2, swr[i + 2], hp[44 + i + 2]);
            ffma2(a3, swr[i + 3], hp[44 + i + 3]);
        }
        float x0, y0, x1, y1, x2, y2, x3, y3;
        unpack2(a0, x0, y0); unpack2(a1, x1, y1);
        unpack2(a2, x2, y2); unpack2(a3, x3, y3);
        z_s[t] = base + ((x0 + y0) + (x1 + y1)) + ((x2 + y2) + (x3 + y3));
        __syncthreads();

        if (t < 128) {
            float zi = z_s[t], zf = z_s[128 + t], zg = z_s[256 + t], zo = z_s[384 + t];
            float ig = fsig(zi);
            float fg = fsig(zf);
            float gg = ftanh(zg);
            float og = fsig(zo);
            c = fg * c + ig * gg;
            float h = og * ftanh(c);
            h_s[t] = h;
            out[((long long)(b * LL + l)) * 256 + dir * HH + t] = h;
        }
        __syncthreads();
    }
}

// ---------------------------------------------------------------------------
// Launch orchestration
// ---------------------------------------------------------------------------
static void* symaddr(const void* sym) {
    void* p = nullptr;
    cudaGetSymbolAddress(&p, sym);
    return p;
}

extern "C" void kernel_launch(void* const* d_in, const int* in_sizes, int n_in,
                              void* d_out, int out_size) {
    const float* x1_word = (const float*)d_in[0];
    const float* x1_a0   = (const float*)d_in[1];
    const float* x1_a1   = (const float*)d_in[2];
    const float* x2_word = (const float*)d_in[3];
    const float* x2_a0   = (const float*)d_in[4];
    const float* x2_a1   = (const float*)d_in[5];
    const float* x2_a2   = (const float*)d_in[6];
    const unsigned char* x2_mask = (const unsigned char*)d_in[8];
    const float* W_attn  = (const float*)d_in[9];
    const float* v_attn  = (const float*)d_in[10];
    const float* Wih_f   = (const float*)d_in[11];
    const float* Whh_f   = (const float*)d_in[12];
    const float* b_f     = (const float*)d_in[13];
    const float* Wih_b   = (const float*)d_in[14];
    const float* Whh_b   = (const float*)d_in[15];
    const float* b_b     = (const float*)d_in[16];
    float* out = (float*)d_out;

    float* x1a = (float*)symaddr(g_x1a);
    float* x2a = (float*)symaddr(g_x2a);
    float* Wc  = (float*)symaddr(g_Wc);
    float* r1  = (float*)symaddr(g_r1);
    float* r2  = (float*)symaddr(g_r2);
    float* sc  = (float*)symaddr(g_sc);
    float* x2T = (float*)symaddr(g_x2T);
    float* x1c = (float*)symaddr(g_x1c);
    float* Wih = (float*)symaddr(g_Wih);
    float* gin = (float*)symaddr(g_gin);

    cudaFuncSetAttribute(lstm_kernel, cudaFuncAttributeMaxDynamicSharedMemorySize,
                         LS_SMEM);

    const float* x2_list[3] = {x2_a0, x2_a1, x2_a2};

    // prep
    {
        long long n1 = (long long)ROWS * K1P;
        bx1<<<(int)((n1 + 255) / 256), 256>>>(x1_word, x1_a0, x1_a1, x1a);
        bx1<<<(int)((n1 + 255) / 256), 256>>>(x2_word, x2_a0, x2_a1, x2a);
        long long nw = (long long)NW * K1P;
        bW<<<(int)((nw + 255) / 256), 256>>>(W_attn, Wc);
    }

    // r1 + r2 FUSED: z=0 -> r1 = relu(x1a @ Wc^T); z=1 -> r2 = relu(x2a @ Wc^T)*v
    gemm_f32<<<dim3(6, 64, 2), 256>>>(
        x1a, Wc, r1, x2a, r2,
        K1P, K1P, NW, K1P / 16,
        0, 0, 0, 0, 0, 0, nullptr, nullptr, v_attn, 1);

    // remaining prep
    {
        long long nh = (long long)1024 * RNN_IN;
        bWih<<<(int)((nh + 255) / 256), 256>>>(Wih_f, Wih_b, Wih);
        long long nc = (long long)ROWS * 2 * AH;
        bcat<<<(int)((nc + 255) / 256), 256>>>(x1_a0, x1_a1, x1c);
        dim3 tg(LL / 32, AH / 32, BB), tb(32, 8);
        for (int i = 0; i < 3; i++)
            btr<<<tg, tb>>>(x2_list[i], x2T + (long long)i * BB * AH * LL);
    }

    // scores[m][b] = r1_sub @ r2_sub^T   (z = m*16+b), K=256
    gemm_f32<<<dim3(4, 4, 48), 256>>>(
        r1, r2, sc, nullptr, nullptr,
        NW, NW, LL, 256 / 16,
        256, (long long)LL * NW,
        256, (long long)LL * NW,
        (long long)BB * LL * LL, (long long)LL * LL,
        nullptr, nullptr, nullptr, 0);

    // softmax in place
    softmax_kernel<<<3 * ROWS, 256>>>(sc, x2_mask);

    // piece[m][b] = alpha @ x2T^T -> x1cat cols [512+256m, +256), K=512
    gemm_f32<<<dim3(2, 4, 48), 256>>>(
        sc, x2T, x1c + 512, nullptr, nullptr,
        LL, LL, RNN_IN, LL / 16,
        (long long)BB * LL * LL, (long long)LL * LL,
        (long long)BB * AH * LL, (long long)AH * LL,
        256, (long long)LL * RNN_IN,
        nullptr, nullptr, nullptr, 0);

    // gin = x1cat @ Wih^T + bias   [8192 x 1024], K=1280
    gemm_f32<<<dim3(8, 64, 1), 256>>>(
        x1c, Wih, gin, nullptr, nullptr,
        RNN_IN, RNN_IN, 1024, RNN_IN / 16,
        0, 0, 0, 0, 0, 0, b_f, b_b, nullptr, 2);

    // recurrence
    lstm_kernel<<<32, 512, LS_SMEM>>>(gin, Whh_f, Whh_b, out);
}

// round 14
// speedup vs baseline: 1.2781x; 1.1183x over previous
#include <cuda_runtime.h>
#include <math.h>
#include <cstdint>

typedef unsigned long long u64;

// ---------------------------------------------------------------------------
// Problem constants
// ---------------------------------------------------------------------------
#define BB   16
#define LL   512
#define EMB  300
#define AH   256
#define ATT  250
#define HH   128
#define ATT_IN 812
#define RNN_IN 1280
#define GATES  512
#define ROWS 8192
#define K1P  816        // ATT_IN padded to 16
#define NW   768        // 3 modules x 256 (ATT padded)

// ---------------------------------------------------------------------------
// Scratch (fp32 everywhere)
// ---------------------------------------------------------------------------
__device__ float g_x1a[ROWS * K1P];
__device__ float g_x2a[ROWS * K1P];
__device__ float g_Wc[NW * K1P];
__device__ float g_r1[ROWS * NW];
__device__ float g_r2[ROWS * NW];
__device__ float g_sc[3ll * BB * LL * LL];
__device__ float g_x2T[3ll * BB * AH * LL];
__device__ float g_x1c[(long long)ROWS * RNN_IN];
__device__ float g_Wih[1024 * RNN_IN];
__device__ float g_gin[(long long)ROWS * 1024];

// ---------------------------------------------------------------------------
// f32x2 helpers
// ---------------------------------------------------------------------------
__device__ __forceinline__ void ffma2(u64& d, u64 a, u64 b) {
    asm("fma.rn.f32x2 %0, %1, %2, %0;" : "+l"(d) : "l"(a), "l"(b));
}
__device__ __forceinline__ u64 dup2(float x) {
    u64 r; asm("mov.b64 %0, {%1, %1};" : "=l"(r) : "f"(x)); return r;
}
__device__ __forceinline__ void unpack2(u64 v, float& x, float& y) {
    asm("mov.b64 {%0, %1}, %2;" : "=f"(x), "=f"(y) : "l"(v));
}

// ---------------------------------------------------------------------------
// Prep kernels
// ---------------------------------------------------------------------------
__global__ void bx1(const float* __restrict__ w, const float* __restrict__ a0,
                    const float* __restrict__ a1, float* __restrict__ out) {
    long long idx = (long long)blockIdx.x * blockDim.x + threadIdx.x;
    if (idx >= (long long)ROWS * K1P) return;
    int r = (int)(idx / K1P), k = (int)(idx % K1P);
    float x = 0.f;
    if (k < EMB)            x = w[r * EMB + k];
    else if (k < EMB + AH)  x = a0[r * AH + (k - EMB)];
    else if (k < ATT_IN)    x = a1[r * AH + (k - EMB - AH)];
    out[idx] = x;
}

__global__ void bW(const float* __restrict__ W, float* __restrict__ out) {
    long long idx = (long long)blockIdx.x * blockDim.x + threadIdx.x;
    if (idx >= (long long)NW * K1P) return;
    int row = (int)(idx / K1P), k = (int)(idx % K1P);
    int m = row >> 8, r = row & 255;
    out[idx] = (r < ATT && k < ATT_IN)
             ? W[((long long)m * ATT + r) * ATT_IN + k] : 0.f;
}

__global__ void bWih(const float* __restrict__ Wf, const float* __restrict__ Wb,
                     float* __restrict__ out) {
    long long idx = (long long)blockIdx.x * blockDim.x + threadIdx.x;
    if (idx >= (long long)1024 * RNN_IN) return;
    int row = (int)(idx / RNN_IN), k = (int)(idx % RNN_IN);
    out[idx] = (row < 512) ? Wf[(long long)row * RNN_IN + k]
                           : Wb[(long long)(row - 512) * RNN_IN + k];
}

__global__ void bcat(const float* __restrict__ a0, const float* __restrict__ a1,
                     float* __restrict__ out) {
    long long idx = (long long)blockIdx.x * blockDim.x + threadIdx.x;
    if (idx >= (long long)ROWS * 2 * AH) return;
    int r = (int)(idx / (2 * AH)), d = (int)(idx % (2 * AH));
    float x = (d < AH) ? a0[r * AH + d] : a1[r * AH + (d - AH)];
    out[(long long)r * RNN_IN + d] = x;
}

// [16][512][256] -> [16][256][512]
__global__ void btr(const float* __restrict__ in, float* __restrict__ out) {
    __shared__ float tile[32][33];
    int b = blockIdx.z;
    int lBase = blockIdx.x * 32, dBase = blockIdx.y * 32;
    const float* ib = in + (long long)b * LL * AH;
    int tx = threadIdx.x, ty = threadIdx.y;   // 32 x 8
#pragma unroll
    for (int i = 0; i < 32; i += 8)
        tile[ty + i][tx] = ib[(long long)(lBase + ty + i) * AH + dBase + tx];
    __syncthreads();
    float* ob = out + (long long)b * AH * LL;
#pragma unroll
    for (int i = 0; i < 32; i += 8)
        ob[(long long)(dBase + ty + i) * LL + lBase + tx] = tile[tx][ty + i];
}

// ---------------------------------------------------------------------------
// fp32 NT GEMM via fma.rn.f32x2.  C = epi(A @ B^T)
// Thread's 8 N-columns are SPLIT [tx*4, tx*4+4) + [64+tx*4, 64+tx*4+4) so the
// two B-fragment LDS.128 are 16B-strided (phase = 128B contiguous) ->
// conflict-free shared reads (was 2-way conflicted with contiguous tx*8).
// Dual mode: if A2 != nullptr, blockIdx.z==1 switches to (A2 -> C2, *vsc).
// ---------------------------------------------------------------------------
__global__ __launch_bounds__(256, 2)
void gemm_f32(const float* __restrict__ A, const float* __restrict__ B,
              float* __restrict__ C,
              const float* __restrict__ A2, float* __restrict__ C2,
              int lda, int ldb, int ldc, int nst,
              long long aHi, long long aLo, long long bHi, long long bLo,
              long long cHi, long long cLo,
              const float* __restrict__ bias0, const float* __restrict__ bias1,
              const float* __restrict__ vsc, int mode) {
    __shared__ float As[2][16][132];
    __shared__ float Bs[2][16][132];
    const int t = threadIdx.x;
    const int tx = t & 15, ty = t >> 4;
    const int m0 = blockIdx.y * 128, n0 = blockIdx.x * 128;
    const int zHi = blockIdx.z >> 4, zLo = blockIdx.z & 15;

    const float* Ag;
    float* Cbase;
    const float* vs;
    if (A2 != nullptr && blockIdx.z == 1) {
        Ag = A2; Cbase = C2; vs = vsc;
    } else {
        Ag = A + (long long)zHi * aHi + (long long)zLo * aLo;
        Cbase = C + (long long)zHi * cHi + (long long)zLo * cLo;
        vs = (A2 == nullptr) ? vsc : nullptr;
    }
    const float* Bg = B + (long long)zHi * bHi + (long long)zLo * bLo;

    u64 acc[8][4];
#pragma unroll
    for (int i = 0; i < 8; i++)
#pragma unroll
        for (int j = 0; j < 4; j++) acc[i][j] = 0ull;

    const int lr = t >> 2, lc = t & 3;
    float4 ra0, ra1, rb0, rb1;

    auto LOADG = [&](int s) {
        const float* pa = Ag + (long long)(m0 + lr) * lda + s * 16 + lc * 4;
        ra0 = *(const float4*)pa;
        ra1 = *(const float4*)(pa + 64ll * lda);
        const float* pb = Bg + (long long)(n0 + lr) * ldb + s * 16 + lc * 4;
        rb0 = *(const float4*)pb;
        rb1 = *(const float4*)(pb + 64ll * ldb);
    };
    auto STS = [&](int buf) {
        As[buf][lc * 4 + 0][lr] = ra0.x; As[buf][lc * 4 + 1][lr] = ra0.y;
        As[buf][lc * 4 + 2][lr] = ra0.z; As[buf][lc * 4 + 3][lr] = ra0.w;
        As[buf][lc * 4 + 0][lr + 64] = ra1.x; As[buf][lc * 4 + 1][lr + 64] = ra1.y;
        As[buf][lc * 4 + 2][lr + 64] = ra1.z; As[buf][lc * 4 + 3][lr + 64] = ra1.w;
        Bs[buf][lc * 4 + 0][lr] = rb0.x; Bs[buf][lc * 4 + 1][lr] = rb0.y;
        Bs[buf][lc * 4 + 2][lr] = rb0.z; Bs[buf][lc * 4 + 3][lr] = rb0.w;
        Bs[buf][lc * 4 + 0][lr + 64] = rb1.x; Bs[buf][lc * 4 + 1][lr + 64] = rb1.y;
        Bs[buf][lc * 4 + 2][lr + 64] = rb1.z; Bs[buf][lc * 4 + 3][lr + 64] = rb1.w;
    };
    auto COMP = [&](int buf) {
#pragma unroll
        for (int k = 0; k < 16; k++) {
            float4 a0 = *(const float4*)&As[buf][k][ty * 8];
            float4 a1 = *(const float4*)&As[buf][k][ty * 8 + 4];
            // B fragments: 16B-strided across tx -> conflict-free phases
            const float* br = &Bs[buf][k][tx * 4];
            ulonglong2 b01 = *(const ulonglong2*)br;          // cols tx*4..+3
            ulonglong2 b23 = *(const ulonglong2*)(br + 64);   // cols 64+tx*4..+3
            u64 bp[4];
            bp[0] = b01.x; bp[1] = b01.y; bp[2] = b23.x; bp[3] = b23.y;
            float av[8] = {a0.x, a0.y, a0.z, a0.w, a1.x, a1.y, a1.z, a1.w};
#pragma unroll
            for (int i = 0; i < 8; i++) {
                u64 ad = dup2(av[i]);
                ffma2(acc[i][0], ad, bp[0]);
                ffma2(acc[i][1], ad, bp[1]);
                ffma2(acc[i][2], ad, bp[2]);
                ffma2(acc[i][3], ad, bp[3]);
            }
        }
    };

    LOADG(0);
    STS(0);
    __syncthreads();
    for (int s = 0; s < nst; s++) {
        if (s + 1 < nst) LOADG(s + 1);
        COMP(s & 1);
        if (s + 1 < nst) {
            STS((s + 1) & 1);
            __syncthreads();
        }
    }

    // Column map: j=0 -> tx*4, j=1 -> tx*4+2, j=2 -> 64+tx*4, j=3 -> 64+tx*4+2
#pragma unroll
    for (int i = 0; i < 8; i++) {
        int gr = m0 + ty * 8 + i;
#pragma unroll
        for (int j = 0; j < 4; j++) {
            float vx, vy;
            unpack2(acc[i][j], vx, vy);
            int gc = n0 + ((j & 2) ? 64 : 0) + tx * 4 + (j & 1) * 2;
            if (mode == 1) {
                vx = fmaxf(vx, 0.f); vy = fmaxf(vy, 0.f);
                if (vs) {
                    int mo = gc >> 8, c = gc & 255;
                    vx *= (c < ATT) ? vs[mo * ATT + c] : 0.f;
                    vy *= (c + 1 < ATT) ? vs[mo * ATT + c + 1] : 0.f;
                }
            } else if (mode == 2) {
                vx += (gc < 512) ? bias0[gc] : bias1[gc - 512];
                vy += (gc + 1 < 512) ? bias0[gc + 1] : bias1[gc - 511];
            }
            float2 w; w.x = vx; w.y = vy;
            *(float2*)(Cbase + (long long)gr * ldc + gc) = w;
        }
    }
}

// ---------------------------------------------------------------------------
// Masked row softmax over L2, in place (fp32).  rows = [module][b][l]
// ---------------------------------------------------------------------------
__global__ void softmax_kernel(float* __restrict__ S,
                               const unsigned char* __restrict__ mask) {
    int row = blockIdx.x;
    int b = (row >> 9) & 15;
    float* s = S + (long long)row * LL;
    const unsigned char* m = mask + (long long)b * LL;
    int t = threadIdx.x;

    __shared__ float red[256];

    float mx = -3.402823466e38f;
    for (int i = t; i < LL; i += 256) {
        float v = m[i] ? -3.402823466e38f : s[i];
        s[i] = v;
        mx = fmaxf(mx, v);
    }
    red[t] = mx; __syncthreads();
    for (int o = 128; o > 0; o >>= 1) {
        if (t < o) red[t] = fmaxf(red[t], red[t + o]);
        __syncthreads();
    }
    mx = red[0]; __syncthreads();

    float sum = 0.f;
    for (int i = t; i < LL; i += 256) {
        float e = __expf(s[i] - mx);
        s[i] = e;
        sum += e;
    }
    red[t] = sum; __syncthreads();
    for (int o = 128; o > 0; o >>= 1) {
        if (t < o) red[t] += red[t + o];
        __syncthreads();
    }
    float inv = 1.f / red[0];
    for (int i = t; i < LL; i += 256) s[i] *= inv;
}

// ---------------------------------------------------------------------------
// BiLSTM recurrence (W in regs+smem, fast activations)
// ---------------------------------------------------------------------------
#define LS_SW_BYTES (512 * 22 * 8)
#define LS_SMEM (LS_SW_BYTES + 128 * 4 + 512 * 4)

__device__ __forceinline__ float fsig(float x) {
    return __fdividef(1.f, 1.f + __expf(-x));
}
__device__ __forceinline__ float ftanh(float x) {
    float e = __expf(-2.f * x);
    return __fdividef(1.f - e, 1.f + e);
}

__global__ __launch_bounds__(512, 1)
void lstm_kernel(const float* __restrict__ gin,
                 const float* __restrict__ Whh_f, const float* __restrict__ Whh_b,
                 float* __restrict__ out) {
    extern __shared__ char ls[];
    u64* sw = (u64*)ls;
    float* h_s = (float*)(ls + LS_SW_BYTES);
    float* z_s = h_s + 128;

    int blk = blockIdx.x;
    int dir = blk >> 4;
    int b = blk & 15;
    const float* W = dir ? Whh_b : Whh_f;
    int t = threadIdx.x;

    // Load W row: k [0,88) -> regs, k [88,128) -> smem
    u64 wreg[44];
    const float* wr = W + t * HH;
#pragma unroll
    for (int i = 0; i < 44; i++) wreg[i] = *(const u64*)(wr + 2 * i);
    u64* swr = sw + t * 22;
#pragma unroll
    for (int i = 0; i < 20; i++) swr[i] = *(const u64*)(wr + 88 + 2 * i);

    if (t < 128) h_s[t] = 0.f;
    float c = 0.f;
    __syncthreads();

    const u64* hp = (const u64*)h_s;    // 64 f32x2 pairs

    for (int step = 0; step < LL; step++) {
        int l = dir ? (LL - 1 - step) : step;
        float base = gin[((long long)(b * LL + l)) * 1024 + dir * 512 + t];

        u64 a0 = 0ull, a1 = 0ull, a2 = 0ull, a3 = 0ull;
#pragma unroll
        for (int i = 0; i < 44; i += 4) {
            ffma2(a0, wreg[i],     hp[i]);
            ffma2(a1, wreg[i + 1], hp[i + 1]);
            ffma2(a2, wreg[i + 2], hp[i + 2]);
            ffma2(a3, wreg[i + 3], hp[i + 3]);
        }
#pragma unroll
        for (int i = 0; i < 20; i += 4) {
            ffma2(a0, swr[i],     hp[44 + i]);
            ffma2(a1, swr[i + 1], hp[44 + i + 1]);
            ffma2(a2, swr[i + 2], hp[44 + i + 2]);
            ffma2(a3, swr[i + 3], hp[44 + i + 3]);
        }
        float x0, y0, x1, y1, x2, y2, x3, y3;
        unpack2(a0, x0, y0); unpack2(a1, x1, y1);
        unpack2(a2, x2, y2); unpack2(a3, x3, y3);
        z_s[t] = base + ((x0 + y0) + (x1 + y1)) + ((x2 + y2) + (x3 + y3));
        __syncthreads();

        if (t < 128) {
            float zi = z_s[t], zf = z_s[128 + t], zg = z_s[256 + t], zo = z_s[384 + t];
            float ig = fsig(zi);
            float fg = fsig(zf);
            float gg = ftanh(zg);
            float og = fsig(zo);
            c = fg * c + ig * gg;
            float h = og * ftanh(c);
            h_s[t] = h;
            out[((long long)(b * LL + l)) * 256 + dir * HH + t] = h;
        }
        __syncthreads();
    }
}

// ---------------------------------------------------------------------------
// Launch orchestration
// ---------------------------------------------------------------------------
static void* symaddr(const void* sym) {
    void* p = nullptr;
    cudaGetSymbolAddress(&p, sym);
    return p;
}

extern "C" void kernel_launch(void* const* d_in, const int* in_sizes, int n_in,
                              void* d_out, int out_size) {
    const float* x1_word = (const float*)d_in[0];
    const float* x1_a0   = (const float*)d_in[1];
    const float* x1_a1   = (const float*)d_in[2];
    const float* x2_word = (const float*)d_in[3];
    const float* x2_a0   = (const float*)d_in[4];
    const float* x2_a1   = (const float*)d_in[5];
    const float* x2_a2   = (const float*)d_in[6];
    const unsigned char* x2_mask = (const unsigned char*)d_in[8];
    const float* W_attn  = (const float*)d_in[9];
    const float* v_attn  = (const float*)d_in[10];
    const float* Wih_f   = (const float*)d_in[11];
    const float* Whh_f   = (const float*)d_in[12];
    const float* b_f     = (const float*)d_in[13];
    const float* Wih_b   = (const float*)d_in[14];
    const float* Whh_b   = (const float*)d_in[15];
    const float* b_b     = (const float*)d_in[16];
    float* out = (float*)d_out;

    float* x1a = (float*)symaddr(g_x1a);
    float* x2a = (float*)symaddr(g_x2a);
    float* Wc  = (float*)symaddr(g_Wc);
    float* r1  = (float*)symaddr(g_r1);
    float* r2  = (float*)symaddr(g_r2);
    float* sc  = (float*)symaddr(g_sc);
    float* x2T = (float*)symaddr(g_x2T);
    float* x1c = (float*)symaddr(g_x1c);
    float* Wih = (float*)symaddr(g_Wih);
    float* gin = (float*)symaddr(g_gin);

    cudaFuncSetAttribute(lstm_kernel, cudaFuncAttributeMaxDynamicSharedMemorySize,
                         LS_SMEM);

    const float* x2_list[3] = {x2_a0, x2_a1, x2_a2};

    // prep
    {
        long long n1 = (long long)ROWS * K1P;
        bx1<<<(int)((n1 + 255) / 256), 256>>>(x1_word, x1_a0, x1_a1, x1a);
        bx1<<<(int)((n1 + 255) / 256), 256>>>(x2_word, x2_a0, x2_a1, x2a);
        long long nw = (long long)NW * K1P;
        bW<<<(int)((nw + 255) / 256), 256>>>(W_attn, Wc);
    }

    // r1 + r2 FUSED: z=0 -> r1 = relu(x1a @ Wc^T); z=1 -> r2 = relu(x2a @ Wc^T)*v
    gemm_f32<<<dim3(6, 64, 2), 256>>>(
        x1a, Wc, r1, x2a, r2,
        K1P, K1P, NW, K1P / 16,
        0, 0, 0, 0, 0, 0, nullptr, nullptr, v_attn, 1);

    // remaining prep
    {
        long long nh = (long long)1024 * RNN_IN;
        bWih<<<(int)((nh + 255) / 256), 256>>>(Wih_f, Wih_b, Wih);
        long long nc = (long long)ROWS * 2 * AH;
        bcat<<<(int)((nc + 255) / 256), 256>>>(x1_a0, x1_a1, x1c);
        dim3 tg(LL / 32, AH / 32, BB), tb(32, 8);
        for (int i = 0; i < 3; i++)
            btr<<<tg, tb>>>(x2_list[i], x2T + (long long)i * BB * AH * LL);
    }

    // scores[m][b] = r1_sub @ r2_sub^T   (z = m*16+b), K=256
    gemm_f32<<<dim3(4, 4, 48), 256>>>(
        r1, r2, sc, nullptr, nullptr,
        NW, NW, LL, 256 / 16,
        256, (long long)LL * NW,
        256, (long long)LL * NW,
        (long long)BB * LL * LL, (long long)LL * LL,
        nullptr, nullptr, nullptr, 0);

    // softmax in place
    softmax_kernel<<<3 * ROWS, 256>>>(sc, x2_mask);

    // piece[m][b] = alpha @ x2T^T -> x1cat cols [512+256m, +256), K=512
    gemm_f32<<<dim3(2, 4, 48), 256>>>(
        sc, x2T, x1c + 512, nullptr, nullptr,
        LL, LL, RNN_IN, LL / 16,
        (long long)BB * LL * LL, (long long)LL * LL,
        (long long)BB * AH * LL, (long long)AH * LL,
        256, (long long)LL * RNN_IN,
        nullptr, nullptr, nullptr, 0);

    // gin = x1cat @ Wih^T + bias   [8192 x 1024], K=1280
    gemm_f32<<<dim3(8, 64, 1), 256>>>(
        x1c, Wih, gin, nullptr, nullptr,
        RNN_IN, RNN_IN, 1024, RNN_IN / 16,
        0, 0, 0, 0, 0, 0, b_f, b_b, nullptr, 2);

    // recurrence
    lstm_kernel<<<32, 512, LS_SMEM>>>(gin, Whh_f, Whh_b, out);
}